// round 14
// baseline (speedup 1.0000x reference)
#include <cuda_runtime.h>
#include <cuda_fp16.h>

// samples: (16,3,480,864) f32 ; encoded: (1,16,480,864) i32 ; n_pixels=2e6
// Both resizes are identity. Task: fp16-round -> fp16 segment mean -> gather.
// Output: float32 (values are fp16 means, promoted).
// Accumulator is fp16 (matches reference's fp16 segment_sum) via f16x2 REDs.

#define N_PIX  2000000
#define T_DIM  16
#define H_DIM  480
#define W_DIM  864
#define HW     (H_DIM * W_DIM)        // 414720  (divisible by 8)
#define NPOS   (T_DIM * HW)           // 6635520
#define N_SAMP (T_DIM * 3 * HW)       // 19906560

// Per bucket 8 bytes: {h0,h1} f16x2 | {h2,count} f16x2.  16 MB — L2-hot.
__device__ uint2 g_acc[N_PIX];

static __device__ __forceinline__ unsigned h2_to_u32(__half2 h) {
    unsigned u; memcpy(&u, &h, 4); return u;
}
static __device__ __forceinline__ __half2 u32_to_h2(unsigned u) {
    __half2 h; memcpy(&h, &u, 4); return h;
}

// ---------------------------------------------------------------------------
// 4 consecutive positions per thread; one 8-byte v2.f16x2 RED per position
// (3 channel sums + count in a single L2 RMW).  LTS-sector-bound (~at cap).
__global__ void scatter_kernel(const float* __restrict__ samples,
                               const int*   __restrict__ enc) {
    int j = blockIdx.x * blockDim.x + threadIdx.x;
    if (j >= NPOS / 4) return;
    int i = 4 * j;
    int t = i / HW;
    int p = i - t * HW;

    const float* s = samples + (size_t)t * 3 * HW + p;
    float4 c0 = *reinterpret_cast<const float4*>(s);
    float4 c1 = *reinterpret_cast<const float4*>(s + HW);
    float4 c2 = *reinterpret_cast<const float4*>(s + 2 * HW);
    int4 idx4 = *reinterpret_cast<const int4*>(enc + i);

    // fp16 rounding matches the reference's .astype(float16) before segment_sum
    #define PK(a, b) h2_to_u32(__floats2half2_rn((a), (b)))
    unsigned p01_x = PK(c0.x, c1.x), p2c_x = PK(c2.x, 1.0f);
    unsigned p01_y = PK(c0.y, c1.y), p2c_y = PK(c2.y, 1.0f);
    unsigned p01_z = PK(c0.z, c1.z), p2c_z = PK(c2.z, 1.0f);
    unsigned p01_w = PK(c0.w, c1.w), p2c_w = PK(c2.w, 1.0f);
    #undef PK

    #define RED2(ix, r0, r1)                                                  \
        asm volatile("red.global.add.noftz.v2.f16x2 [%0], {%1, %2};"          \
                     :: "l"(&g_acc[ix]), "r"(r0), "r"(r1) : "memory")
    RED2(idx4.x, p01_x, p2c_x);
    RED2(idx4.y, p01_y, p2c_y);
    RED2(idx4.z, p01_z, p2c_z);
    RED2(idx4.w, p01_w, p2c_w);
    #undef RED2
}

// ---------------------------------------------------------------------------
// Fused divide + gather: 8 positions/thread for doubled MLP on the random
// 8B table reads.  __launch_bounds__ caps regs to protect occupancy
// (R9 lesson: reg blowup -> occ crash -> regression).
__global__ void __launch_bounds__(256, 6)
gather_kernel(const int* __restrict__ enc,
              float*     __restrict__ out) {
    int j = blockIdx.x * blockDim.x + threadIdx.x;
    if (j >= NPOS / 8) return;
    int i = 8 * j;
    int t = i / HW;
    int p = i - t * HW;

    int4 ia = *reinterpret_cast<const int4*>(enc + i);
    int4 ib = *reinterpret_cast<const int4*>(enc + i + 4);

    uint2 a0 = __ldg(&g_acc[ia.x]);
    uint2 a1 = __ldg(&g_acc[ia.y]);
    uint2 a2 = __ldg(&g_acc[ia.z]);
    uint2 a3 = __ldg(&g_acc[ia.w]);
    uint2 a4 = __ldg(&g_acc[ib.x]);
    uint2 a5 = __ldg(&g_acc[ib.y]);
    uint2 a6 = __ldg(&g_acc[ib.z]);
    uint2 a7 = __ldg(&g_acc[ib.w]);

    float r0[8], r1[8], r2[8];
    #define FIN(k, A) {                                                       \
        __half2 s01 = u32_to_h2((A).x);                                       \
        __half2 s2c = u32_to_h2((A).y);                                       \
        float inv = 1.0f / __half2float(__high2half(s2c)); /* count >= 1 */   \
        r0[k] = __half2float(__float2half_rn(__half2float(__low2half(s01))  * inv)); \
        r1[k] = __half2float(__float2half_rn(__half2float(__high2half(s01)) * inv)); \
        r2[k] = __half2float(__float2half_rn(__half2float(__low2half(s2c))  * inv)); \
    }
    FIN(0, a0) FIN(1, a1) FIN(2, a2) FIN(3, a3)
    FIN(4, a4) FIN(5, a5) FIN(6, a6) FIN(7, a7)
    #undef FIN

    float* o = out + (size_t)t * 3 * HW + p;
    #define ST8(row, r)                                                       \
        *reinterpret_cast<float4*>(o + (row) * HW)     =                      \
            make_float4((r)[0], (r)[1], (r)[2], (r)[3]);                      \
        *reinterpret_cast<float4*>(o + (row) * HW + 4) =                      \
            make_float4((r)[4], (r)[5], (r)[6], (r)[7]);
    ST8(0, r0) ST8(1, r1) ST8(2, r2)
    #undef ST8
}

// ---------------------------------------------------------------------------
extern "C" void kernel_launch(void* const* d_in, const int* in_sizes, int n_in,
                              void* d_out, int out_size) {
    const float* samples = nullptr;
    const int*   enc     = nullptr;
    for (int k = 0; k < n_in; k++) {
        if (in_sizes[k] == N_SAMP)    samples = (const float*)d_in[k];
        else if (in_sizes[k] == NPOS) enc     = (const int*)d_in[k];
    }
    float* out = (float*)d_out;

    // Zero the 16 MB accumulator with a memset node.
    void* acc_ptr = nullptr;
    cudaGetSymbolAddress(&acc_ptr, g_acc);
    cudaMemsetAsync(acc_ptr, 0, (size_t)N_PIX * sizeof(uint2));

    const int TPB = 256;
    scatter_kernel<<<(NPOS / 4 + TPB - 1) / TPB, TPB>>>(samples, enc);
    gather_kernel<<<(NPOS / 8 + TPB - 1) / TPB, TPB>>>(enc, out);
}

// round 15
// speedup vs baseline: 1.1024x; 1.1024x over previous
#include <cuda_runtime.h>
#include <cuda_fp16.h>

// samples: (16,3,480,864) f32 ; encoded: (1,16,480,864) i32 ; n_pixels=2e6
// Both resizes are identity. Task: fp16-round -> fp16 segment mean -> gather.
// Output: float32 (values are fp16 means, promoted).
// Accumulator is fp16 (matches reference's fp16 segment_sum) via f16x2 REDs.

#define N_PIX  2000000
#define T_DIM  16
#define H_DIM  480
#define W_DIM  864
#define HW     (H_DIM * W_DIM)        // 414720  (divisible by 8)
#define NPOS   (T_DIM * HW)           // 6635520
#define N_SAMP (T_DIM * 3 * HW)       // 19906560

// Per bucket 8 bytes: {h0,h1} f16x2 | {h2,count} f16x2.  16 MB — L2-hot.
__device__ uint2 g_acc[N_PIX];

static __device__ __forceinline__ unsigned h2_to_u32(__half2 h) {
    unsigned u; memcpy(&u, &h, 4); return u;
}
static __device__ __forceinline__ __half2 u32_to_h2(unsigned u) {
    __half2 h; memcpy(&h, &u, 4); return h;
}

// ---------------------------------------------------------------------------
// 4 consecutive positions per thread; one 8-byte v2.f16x2 RED per position
// (3 channel sums + count in a single L2 RMW).  LTS-sector-bound (~at cap).
__global__ void scatter_kernel(const float* __restrict__ samples,
                               const int*   __restrict__ enc) {
    int j = blockIdx.x * blockDim.x + threadIdx.x;
    if (j >= NPOS / 4) return;
    int i = 4 * j;
    int t = i / HW;
    int p = i - t * HW;

    const float* s = samples + (size_t)t * 3 * HW + p;
    float4 c0 = *reinterpret_cast<const float4*>(s);
    float4 c1 = *reinterpret_cast<const float4*>(s + HW);
    float4 c2 = *reinterpret_cast<const float4*>(s + 2 * HW);
    int4 idx4 = *reinterpret_cast<const int4*>(enc + i);

    // fp16 rounding matches the reference's .astype(float16) before segment_sum
    #define PK(a, b) h2_to_u32(__floats2half2_rn((a), (b)))
    unsigned p01_x = PK(c0.x, c1.x), p2c_x = PK(c2.x, 1.0f);
    unsigned p01_y = PK(c0.y, c1.y), p2c_y = PK(c2.y, 1.0f);
    unsigned p01_z = PK(c0.z, c1.z), p2c_z = PK(c2.z, 1.0f);
    unsigned p01_w = PK(c0.w, c1.w), p2c_w = PK(c2.w, 1.0f);
    #undef PK

    #define RED2(ix, r0, r1)                                                  \
        asm volatile("red.global.add.noftz.v2.f16x2 [%0], {%1, %2};"          \
                     :: "l"(&g_acc[ix]), "r"(r0), "r"(r1) : "memory")
    RED2(idx4.x, p01_x, p2c_x);
    RED2(idx4.y, p01_y, p2c_y);
    RED2(idx4.z, p01_z, p2c_z);
    RED2(idx4.w, p01_w, p2c_w);
    #undef RED2
}

// ---------------------------------------------------------------------------
// Fused divide + gather, R12 shape (4 pos/thread — measured-best occupancy).
// Table + enc reads via __ldcg: L2-only, no L1 allocate. The 16 MB table is
// randomly accessed with ~0% L1 reuse, so L1 fills are pure overhead on the
// L1tex pipe (75.7% busy in R12).
__global__ void gather_kernel(const int* __restrict__ enc,
                              float*     __restrict__ out) {
    int j = blockIdx.x * blockDim.x + threadIdx.x;
    if (j >= NPOS / 4) return;
    int i = 4 * j;
    int t = i / HW;
    int p = i - t * HW;

    int4 idx4 = __ldcg(reinterpret_cast<const int4*>(enc + i));
    uint2 a = __ldcg(&g_acc[idx4.x]);
    uint2 b = __ldcg(&g_acc[idx4.y]);
    uint2 c = __ldcg(&g_acc[idx4.z]);
    uint2 d = __ldcg(&g_acc[idx4.w]);

    float r0[4], r1[4], r2[4];
    #define FIN(k, A) {                                                       \
        __half2 s01 = u32_to_h2((A).x);                                       \
        __half2 s2c = u32_to_h2((A).y);                                       \
        float inv = 1.0f / __half2float(__high2half(s2c)); /* count >= 1 */   \
        r0[k] = __half2float(__float2half_rn(__half2float(__low2half(s01))  * inv)); \
        r1[k] = __half2float(__float2half_rn(__half2float(__high2half(s01)) * inv)); \
        r2[k] = __half2float(__float2half_rn(__half2float(__low2half(s2c))  * inv)); \
    }
    FIN(0, a) FIN(1, b) FIN(2, c) FIN(3, d)
    #undef FIN

    float* o = out + (size_t)t * 3 * HW + p;
    *reinterpret_cast<float4*>(o)          = make_float4(r0[0], r0[1], r0[2], r0[3]);
    *reinterpret_cast<float4*>(o + HW)     = make_float4(r1[0], r1[1], r1[2], r1[3]);
    *reinterpret_cast<float4*>(o + 2 * HW) = make_float4(r2[0], r2[1], r2[2], r2[3]);
}

// ---------------------------------------------------------------------------
extern "C" void kernel_launch(void* const* d_in, const int* in_sizes, int n_in,
                              void* d_out, int out_size) {
    const float* samples = nullptr;
    const int*   enc     = nullptr;
    for (int k = 0; k < n_in; k++) {
        if (in_sizes[k] == N_SAMP)    samples = (const float*)d_in[k];
        else if (in_sizes[k] == NPOS) enc     = (const int*)d_in[k];
    }
    float* out = (float*)d_out;

    // Zero the 16 MB accumulator with a memset node.
    void* acc_ptr = nullptr;
    cudaGetSymbolAddress(&acc_ptr, g_acc);
    cudaMemsetAsync(acc_ptr, 0, (size_t)N_PIX * sizeof(uint2));

    const int TPB = 256;
    scatter_kernel<<<(NPOS / 4 + TPB - 1) / TPB, TPB>>>(samples, enc);
    gather_kernel<<<(NPOS / 4 + TPB - 1) / TPB, TPB>>>(enc, out);
}

// round 16
// speedup vs baseline: 1.1247x; 1.0202x over previous
#include <cuda_runtime.h>
#include <cuda_fp16.h>

// samples: (16,3,480,864) f32 ; encoded: (1,16,480,864) i32 ; n_pixels=2e6
// Both resizes are identity. Task: fp16-round -> fp16 segment mean -> gather.
// Output: float32 (values are fp16 means, promoted).
// Accumulator is fp16 (matches reference's fp16 segment_sum) via f16x2 REDs.
//
// Measured component floors (ncu, R10-R14): memset 2.5us, scatter ~43us
// (REDG op-rate bound, 6.6M ops), gather ~38.5us (L1tex wavefront bound,
// 1 wf per random lane read).  This round: protect enc+acc L2 residency by
// marking the read-once samples stream evict-first (__ldcs).

#define N_PIX  2000000
#define T_DIM  16
#define H_DIM  480
#define W_DIM  864
#define HW     (H_DIM * W_DIM)        // 414720  (divisible by 8)
#define NPOS   (T_DIM * HW)           // 6635520
#define N_SAMP (T_DIM * 3 * HW)       // 19906560

// Per bucket 8 bytes: {h0,h1} f16x2 | {h2,count} f16x2.  16 MB — L2-hot.
__device__ uint2 g_acc[N_PIX];

static __device__ __forceinline__ unsigned h2_to_u32(__half2 h) {
    unsigned u; memcpy(&u, &h, 4); return u;
}
static __device__ __forceinline__ __half2 u32_to_h2(unsigned u) {
    __half2 h; memcpy(&h, &u, 4); return h;
}

// ---------------------------------------------------------------------------
// 4 consecutive positions per thread; one 8-byte v2.f16x2 RED per position
// (3 channel sums + count in a single L2 RMW).  REDG-op-rate bound.
// samples via __ldcs (read-once stream, evict-first: keeps enc+acc in L2).
__global__ void scatter_kernel(const float* __restrict__ samples,
                               const int*   __restrict__ enc) {
    int j = blockIdx.x * blockDim.x + threadIdx.x;
    if (j >= NPOS / 4) return;
    int i = 4 * j;
    int t = i / HW;
    int p = i - t * HW;

    const float* s = samples + (size_t)t * 3 * HW + p;
    float4 c0 = __ldcs(reinterpret_cast<const float4*>(s));
    float4 c1 = __ldcs(reinterpret_cast<const float4*>(s + HW));
    float4 c2 = __ldcs(reinterpret_cast<const float4*>(s + 2 * HW));
    int4 idx4 = *reinterpret_cast<const int4*>(enc + i);   // keep cached: reused by gather

    // fp16 rounding matches the reference's .astype(float16) before segment_sum
    #define PK(a, b) h2_to_u32(__floats2half2_rn((a), (b)))
    unsigned p01_x = PK(c0.x, c1.x), p2c_x = PK(c2.x, 1.0f);
    unsigned p01_y = PK(c0.y, c1.y), p2c_y = PK(c2.y, 1.0f);
    unsigned p01_z = PK(c0.z, c1.z), p2c_z = PK(c2.z, 1.0f);
    unsigned p01_w = PK(c0.w, c1.w), p2c_w = PK(c2.w, 1.0f);
    #undef PK

    #define RED2(ix, r0, r1)                                                  \
        asm volatile("red.global.add.noftz.v2.f16x2 [%0], {%1, %2};"          \
                     :: "l"(&g_acc[ix]), "r"(r0), "r"(r1) : "memory")
    RED2(idx4.x, p01_x, p2c_x);
    RED2(idx4.y, p01_y, p2c_y);
    RED2(idx4.z, p01_z, p2c_z);
    RED2(idx4.w, p01_w, p2c_w);
    #undef RED2
}

// ---------------------------------------------------------------------------
// Fused divide + gather, measured-best shape: 4 pos/thread, regs 28, occ 83%.
__global__ void gather_kernel(const int* __restrict__ enc,
                              float*     __restrict__ out) {
    int j = blockIdx.x * blockDim.x + threadIdx.x;
    if (j >= NPOS / 4) return;
    int i = 4 * j;
    int t = i / HW;
    int p = i - t * HW;

    int4 idx4 = *reinterpret_cast<const int4*>(enc + i);
    uint2 a = __ldg(&g_acc[idx4.x]);
    uint2 b = __ldg(&g_acc[idx4.y]);
    uint2 c = __ldg(&g_acc[idx4.z]);
    uint2 d = __ldg(&g_acc[idx4.w]);

    float r0[4], r1[4], r2[4];
    #define FIN(k, A) {                                                       \
        __half2 s01 = u32_to_h2((A).x);                                       \
        __half2 s2c = u32_to_h2((A).y);                                       \
        float inv = 1.0f / __half2float(__high2half(s2c)); /* count >= 1 */   \
        r0[k] = __half2float(__float2half_rn(__half2float(__low2half(s01))  * inv)); \
        r1[k] = __half2float(__float2half_rn(__half2float(__high2half(s01)) * inv)); \
        r2[k] = __half2float(__float2half_rn(__half2float(__low2half(s2c))  * inv)); \
    }
    FIN(0, a) FIN(1, b) FIN(2, c) FIN(3, d)
    #undef FIN

    float* o = out + (size_t)t * 3 * HW + p;
    *reinterpret_cast<float4*>(o)          = make_float4(r0[0], r0[1], r0[2], r0[3]);
    *reinterpret_cast<float4*>(o + HW)     = make_float4(r1[0], r1[1], r1[2], r1[3]);
    *reinterpret_cast<float4*>(o + 2 * HW) = make_float4(r2[0], r2[1], r2[2], r2[3]);
}

// ---------------------------------------------------------------------------
extern "C" void kernel_launch(void* const* d_in, const int* in_sizes, int n_in,
                              void* d_out, int out_size) {
    const float* samples = nullptr;
    const int*   enc     = nullptr;
    for (int k = 0; k < n_in; k++) {
        if (in_sizes[k] == N_SAMP)    samples = (const float*)d_in[k];
        else if (in_sizes[k] == NPOS) enc     = (const int*)d_in[k];
    }
    float* out = (float*)d_out;

    // Zero the 16 MB accumulator with a memset node.
    void* acc_ptr = nullptr;
    cudaGetSymbolAddress(&acc_ptr, g_acc);
    cudaMemsetAsync(acc_ptr, 0, (size_t)N_PIX * sizeof(uint2));

    const int TPB = 256;
    scatter_kernel<<<(NPOS / 4 + TPB - 1) / TPB, TPB>>>(samples, enc);
    gather_kernel<<<(NPOS / 4 + TPB - 1) / TPB, TPB>>>(enc, out);
}